// round 5
// baseline (speedup 1.0000x reference)
#include <cuda_runtime.h>
#include <math.h>

// ---------------------------------------------------------------------------
// ModalUncertaintyEstimator  (B=64, C=8, H=256, M=32)   -- f32x2 packed-FMA rev
// ---------------------------------------------------------------------------

#define BC        512
#define HH        256
#define NIMG      1024          // pred images [0,512) then gt images [512,1024)
#define IMG_ELEMS 65536
#define MODES     1024
#define FEPS      1e-8f

// ---- output layout (concatenated reference tuple, all float32) ----
#define OFF_EN    0
#define OFF_UNC   524288
#define OFF_FRAC  1048576
#define OFF_WIMP  1572864
#define OFF_USPEC 2097152
#define OFF_ESPEC 2098176
#define OFF_ERR   2099200
#define OFF_CAL   2623488

typedef unsigned long long u64;

// ---- f32x2 helpers -------------------------------------------------------
__device__ __forceinline__ u64 pack2(float lo, float hi) {
    u64 r; asm("mov.b64 %0, {%1, %2};" : "=l"(r) : "f"(lo), "f"(hi)); return r;
}
__device__ __forceinline__ void unpack2(u64 v, float& lo, float& hi) {
    asm("mov.b64 {%0, %1}, %2;" : "=f"(lo), "=f"(hi) : "l"(v));
}
__device__ __forceinline__ u64 fma2(u64 a, u64 b, u64 c) {
    u64 d; asm("fma.rn.f32x2 %0, %1, %2, %3;" : "=l"(d) : "l"(a), "l"(b), "l"(c));
    return d;
}

// ---- scratch -------------------------------------------------------------
__device__ float g_T[(size_t)NIMG * HH * 64];   // [img][x][0:32]=Tr, [32:64]=Ti
__device__ float g_mre[(size_t)NIMG * MODES];
__device__ float g_mim[(size_t)NIMG * MODES];
__device__ float g_total[BC];

// ===========================================================================
// Stage 1: T[x][k] = sum_y P[x][y] * exp(-2*pi*i*k*y/256), k = 0..31.
// Folded over y with a uniform 129-entry table:
//   e[y] = P[y]+P[(256-y)&255], o[y] = P[(256-y)&255]-P[y], y = 0..128
//   tab(y,k) = (cos, sin)(2*pi*y*k/256) * (y==0||y==128 ? 0.5 : 1)
//   Tr[k] = sum_y e[y]*c(y,k) ;  Ti[k] = sum_y o[y]*s(y,k)
// ===========================================================================
#define S1_TAB_F4   (129 * 16)
#define S1_PT_OFF   (S1_TAB_F4 * 4)       // float index of Pt
#define S1_PTSTRIDE 260
#define S1_SMEM     (S1_TAB_F4 * 16 + 64 * S1_PTSTRIDE * 4)   // 99,584 B

__global__ __launch_bounds__(128) void k_stage1(const float* __restrict__ pred,
                                                const float* __restrict__ gt)
{
    extern __shared__ float smem[];
    float4* tab4 = (float4*)smem;
    float*  Pt   = smem + S1_PT_OFF;

    const int img = blockIdx.x;
    const float* src = (img < BC) ? (pred + (size_t)img * IMG_ELEMS)
                                  : (gt   + (size_t)(img - BC) * IMG_ELEMS);
    const int tid = threadIdx.x;

    // twiddle table (c0,c1,s0,s1) per (y, kpair); endpoint rows scaled by 0.5
    for (int i = tid; i < S1_TAB_F4; i += 128) {
        int y  = i >> 4;
        int kp = i & 15;
        int k0 = 2 * kp, k1 = 2 * kp + 1;
        float a0 = (float)((y * k0) & 255) * (1.0f / 128.0f);
        float a1 = (float)((y * k1) & 255) * (1.0f / 128.0f);
        float sc = (y == 0 || y == 128) ? 0.5f : 1.0f;
        tab4[i] = make_float4(sc * cospif(a0), sc * cospif(a1),
                              sc * sinpif(a0), sc * sinpif(a1));
    }

    const int kg = tid & 3;          // k base = kg*8 (4 k-pairs)
    const int rg = tid >> 2;         // rows rg and rg+32 within tile
    float* Trow = g_T + (size_t)img * HH * 64;

    for (int tile = 0; tile < 4; ++tile) {
        const int x0 = tile * 64;
        __syncthreads();             // table ready (tile 0) / Pt readers done
        {
            const float4* g4 = (const float4*)(src + (size_t)x0 * HH);
            for (int i = tid; i < 64 * 64; i += 128) {
                int row = i >> 6;
                int col = (i & 63) * 4;
                *(float4*)&Pt[row * S1_PTSTRIDE + col] = g4[i];
            }
        }
        __syncthreads();

        u64 tr0[4], ti0[4], tr1[4], ti1[4];
        #pragma unroll
        for (int p = 0; p < 4; ++p) { tr0[p]=0; ti0[p]=0; tr1[p]=0; ti1[p]=0; }

        const float* rowA = &Pt[rg * S1_PTSTRIDE];
        const float* rowB = &Pt[(rg + 32) * S1_PTSTRIDE];
        const float4* tp  = &tab4[kg * 4];

        #pragma unroll 2
        for (int y = 0; y <= 128; ++y) {
            int by = (256 - y) & 255;
            float a0 = rowA[y], b0 = rowA[by];
            float a1 = rowB[y], b1 = rowB[by];
            u64 e20 = pack2(a0 + b0, a0 + b0);
            u64 o20 = pack2(b0 - a0, b0 - a0);
            u64 e21 = pack2(a1 + b1, a1 + b1);
            u64 o21 = pack2(b1 - a1, b1 - a1);
            const float4* t = tp + y * 16;
            #pragma unroll
            for (int p = 0; p < 4; ++p) {
                float4 w = t[p];
                u64 c2 = pack2(w.x, w.y);
                u64 s2 = pack2(w.z, w.w);
                tr0[p] = fma2(e20, c2, tr0[p]);
                ti0[p] = fma2(o20, s2, ti0[p]);
                tr1[p] = fma2(e21, c2, tr1[p]);
                ti1[p] = fma2(o21, s2, ti1[p]);
            }
        }

        // store: Tr at cols [kg*8 .. kg*8+7], Ti at +32 (16B-aligned v2.u64)
        {
            float* dA = Trow + (size_t)(x0 + rg) * 64 + kg * 8;
            float* dB = Trow + (size_t)(x0 + rg + 32) * 64 + kg * 8;
            ((ulonglong2*)dA)[0]        = make_ulonglong2(tr0[0], tr0[1]);
            ((ulonglong2*)(dA + 4))[0]  = make_ulonglong2(tr0[2], tr0[3]);
            ((ulonglong2*)(dA + 32))[0] = make_ulonglong2(ti0[0], ti0[1]);
            ((ulonglong2*)(dA + 36))[0] = make_ulonglong2(ti0[2], ti0[3]);
            ((ulonglong2*)dB)[0]        = make_ulonglong2(tr1[0], tr1[1]);
            ((ulonglong2*)(dB + 4))[0]  = make_ulonglong2(tr1[2], tr1[3]);
            ((ulonglong2*)(dB + 32))[0] = make_ulonglong2(ti1[0], ti1[1]);
            ((ulonglong2*)(dB + 36))[0] = make_ulonglong2(ti1[2], ti1[3]);
        }
    }
}

// ===========================================================================
// Stage 2: modes[k1][k2] = sum_x exp(-2*pi*i*k1*x/256) * T[x][k2], folded in x.
// acc[k1] packs (re,im) as f32x2.  ccss[m] = (c,c,s,s) removes dup-MOVs.
// ===========================================================================
__global__ __launch_bounds__(128) void k_stage2(float* __restrict__ out)
{
    __shared__ float4 ccss[256];
    __shared__ float  red[128];

    const int img = blockIdx.x;
    const int tid = threadIdx.x;

    for (int i = tid; i < 256; i += 128) {
        float a = (float)i * (1.0f / 128.0f);
        float c = cospif(a), s = sinpif(a);
        ccss[i] = make_float4(c, c, s, s);
    }
    __syncthreads();

    const int lane = tid & 31;           // k2
    const int k1b  = (tid >> 5) * 8;     // k1 base for this warp
    const float* T = g_T + (size_t)img * HH * 64;

    u64 acc[8];                          // (re, im) per k1
    #pragma unroll
    for (int i = 0; i < 8; ++i) acc[i] = 0;

    for (int x = 1; x <= 127; ++x) {
        float tra = T[x * 64 + lane];
        float tia = T[x * 64 + 32 + lane];
        float trb = T[(256 - x) * 64 + lane];
        float tib = T[(256 - x) * 64 + 32 + lane];
        u64 A2 = pack2(tra + trb, tia + tib);        // (Etr, Eti)
        u64 B2 = pack2(tia - tib, trb - tra);        // (Oti, -Otr)
        int m = (x * k1b) & 255;
        #pragma unroll
        for (int i = 0; i < 8; ++i) {
            float4 f = ccss[m];
            u64 cc = pack2(f.x, f.y);
            u64 ss = pack2(f.z, f.w);
            acc[i] = fma2(cc, A2, acc[i]);
            acc[i] = fma2(ss, B2, acc[i]);
            m = (m + x) & 255;
        }
    }

    // endpoints x=0 and x=128
    float tr0   = T[lane],            ti0   = T[32 + lane];
    float tr128 = T[128 * 64 + lane], ti128 = T[128 * 64 + 32 + lane];

    const size_t mbase = (size_t)img * MODES;
    float esum = 0.f;
    #pragma unroll
    for (int i = 0; i < 8; ++i) {
        float re, im;
        unpack2(acc[i], re, im);
        float sgn = ((k1b + i) & 1) ? -1.0f : 1.0f;
        re += tr0 + sgn * tr128;
        im += ti0 + sgn * ti128;
        int idx = (k1b + i) * 32 + lane;
        g_mre[mbase + idx] = re;
        g_mim[mbase + idx] = im;
        if (img < BC) {
            float en = re * re + im * im;
            out[OFF_EN + (size_t)img * MODES + idx] = en;
            esum += en;
        }
    }

    if (img < BC) {
        red[tid] = esum;
        __syncthreads();
        for (int s = 64; s > 0; s >>= 1) {
            if (tid < s) red[tid] += red[tid + s];
            __syncthreads();
        }
        if (tid == 0) g_total[img] = red[0];
    }
}

// ===========================================================================
// MLP per mode (2->64->32->1, softplus) + element-wise outputs.  f32x2 inner.
// ===========================================================================
__global__ __launch_bounds__(256) void k_mlp(
    const float* __restrict__ W1, const float* __restrict__ b1,
    const float* __restrict__ W2, const float* __restrict__ b2,
    const float* __restrict__ W3, const float* __restrict__ b3,
    float* __restrict__ out)
{
    __shared__ float sW1[128];
    __shared__ float sb1[64];
    __shared__ __align__(16) float sW2[2048];   // [64][32]
    __shared__ __align__(16) float sb2[32];
    __shared__ float sW3[32];
    __shared__ float sb3;

    const int tid = threadIdx.x;
    for (int i = tid; i < 128;  i += 256) sW1[i] = W1[i];
    for (int i = tid; i < 2048; i += 256) sW2[i] = W2[i];
    if (tid < 64) sb1[tid] = b1[tid];
    if (tid < 32) { sb2[tid] = b2[tid]; sW3[tid] = W3[tid]; }
    if (tid == 0) sb3 = b3[0];
    __syncthreads();

    const size_t g = (size_t)blockIdx.x * 256 + tid;
    const int bc = (int)(g >> 10);

    float xr = g_mre[g];
    float xv = g_mim[g];
    float gr = g_mre[(size_t)BC * MODES + g];
    float gi = g_mim[(size_t)BC * MODES + g];

    u64 acc2[16];
    #pragma unroll
    for (int j = 0; j < 16; ++j) acc2[j] = ((const u64*)sb2)[j];

    #pragma unroll 4
    for (int i = 0; i < 64; ++i) {
        float h = fmaf(xr, sW1[i], fmaf(xv, sW1[64 + i], sb1[i]));
        h = fmaxf(h, 0.f);
        u64 h2 = pack2(h, h);
        const uint4* w4 = (const uint4*)&sW2[i * 32];
        #pragma unroll
        for (int q = 0; q < 8; ++q) {
            uint4 w = w4[q];
            u64 wlo, whi;
            asm("mov.b64 %0, {%1, %2};" : "=l"(wlo) : "r"(w.x), "r"(w.y));
            asm("mov.b64 %0, {%1, %2};" : "=l"(whi) : "r"(w.z), "r"(w.w));
            acc2[2 * q]     = fma2(h2, wlo, acc2[2 * q]);
            acc2[2 * q + 1] = fma2(h2, whi, acc2[2 * q + 1]);
        }
    }

    float z = sb3;
    #pragma unroll
    for (int j = 0; j < 16; ++j) {
        float lo, hi;
        unpack2(acc2[j], lo, hi);
        z = fmaf(fmaxf(lo, 0.f), sW3[2 * j],     z);
        z = fmaf(fmaxf(hi, 0.f), sW3[2 * j + 1], z);
    }

    float u = fmaxf(z, 0.f) + log1pf(expf(-fabsf(z)));   // softplus

    float en   = xr * xr + xv * xv;
    float frac = en / (g_total[bc] + FEPS);
    float dr = xr - gr, di = xv - gi;
    float err = dr * dr + di * di;

    out[OFF_UNC  + g] = u;
    out[OFF_FRAC + g] = frac;
    out[OFF_WIMP + g] = frac * u;
    out[OFF_ERR  + g] = err;
}

// ===========================================================================
// Per-mode reductions: spectra means + Pearson(u, err) over 512 (b,c).
// ===========================================================================
__global__ __launch_bounds__(128) void k_pearson(float* __restrict__ out)
{
    __shared__ float su[512], se[512];
    __shared__ float r1[128], r2[128], r3[128];

    const int mode = blockIdx.x;
    const int tid  = threadIdx.x;

    const float* unc = out + OFF_UNC;
    const float* err = out + OFF_ERR;
    const float* eng = out + OFF_EN;

    float lu = 0.f, le = 0.f, len = 0.f;
    #pragma unroll
    for (int r = 0; r < 4; ++r) {
        int bc = tid + r * 128;
        float u = unc[(size_t)bc * MODES + mode];
        float e = err[(size_t)bc * MODES + mode];
        float n = eng[(size_t)bc * MODES + mode];
        su[bc] = u; se[bc] = e;
        lu += u; le += e; len += n;
    }
    r1[tid] = lu; r2[tid] = le; r3[tid] = len;
    __syncthreads();
    for (int s = 64; s > 0; s >>= 1) {
        if (tid < s) { r1[tid] += r1[tid + s]; r2[tid] += r2[tid + s]; r3[tid] += r3[tid + s]; }
        __syncthreads();
    }
    const float SU = r1[0], SE = r2[0], SEN = r3[0];
    const float mu = SU * (1.0f / 512.0f);
    const float me = SE * (1.0f / 512.0f);
    __syncthreads();

    float s1 = 0.f, s2 = 0.f, s3 = 0.f;
    #pragma unroll
    for (int r = 0; r < 4; ++r) {
        int bc = tid + r * 128;
        float uc = su[bc] - mu;
        float ec = se[bc] - me;
        s1 += uc * ec; s2 += uc * uc; s3 += ec * ec;
    }
    r1[tid] = s1; r2[tid] = s2; r3[tid] = s3;
    __syncthreads();
    for (int s = 64; s > 0; s >>= 1) {
        if (tid < s) { r1[tid] += r1[tid + s]; r2[tid] += r2[tid + s]; r3[tid] += r3[tid + s]; }
        __syncthreads();
    }

    if (tid == 0) {
        out[OFF_USPEC + mode] = SU  * (1.0f / 512.0f);
        out[OFF_ESPEC + mode] = SEN * (1.0f / 512.0f);
        float den = sqrtf(r2[0] * r3[0]);
        out[OFF_CAL + mode] = r1[0] / (den + FEPS);
    }
}

// ===========================================================================
extern "C" void kernel_launch(void* const* d_in, const int* in_sizes, int n_in,
                              void* d_out, int out_size)
{
    (void)in_sizes; (void)n_in; (void)out_size;
    const float* pred = (const float*)d_in[0];
    // d_in[1] ('uncertainty') is unused by the reference computation.
    const float* gt   = (const float*)d_in[2];
    const float* W1   = (const float*)d_in[3];
    const float* b1   = (const float*)d_in[4];
    const float* W2   = (const float*)d_in[5];
    const float* b2   = (const float*)d_in[6];
    const float* W3   = (const float*)d_in[7];
    const float* b3   = (const float*)d_in[8];
    float* out = (float*)d_out;

    cudaFuncSetAttribute(k_stage1, cudaFuncAttributeMaxDynamicSharedMemorySize,
                         S1_SMEM);

    k_stage1 <<<NIMG, 128, S1_SMEM>>>(pred, gt);
    k_stage2 <<<NIMG, 128>>>(out);
    k_mlp    <<<2048, 256>>>(W1, b1, W2, b2, W3, b3, out);
    k_pearson<<<MODES, 128>>>(out);
}

// round 8
// speedup vs baseline: 1.2324x; 1.2324x over previous
#include <cuda_runtime.h>
#include <math.h>

// ---------------------------------------------------------------------------
// ModalUncertaintyEstimator  (B=64, C=8, H=256, M=32)
// Scalar-FFMA rev (f32x2 reverted: regressed on sm_100a).
// Stage-1 register-blocked 2 rows x 8 k per thread.
// ---------------------------------------------------------------------------

#define BC        512
#define HH        256
#define NIMG      1024          // pred images [0,512) then gt images [512,1024)
#define IMG_ELEMS 65536
#define MODES     1024
#define FEPS      1e-8f

// ---- output layout (concatenated reference tuple, all float32) ----
#define OFF_EN    0
#define OFF_UNC   524288
#define OFF_FRAC  1048576
#define OFF_WIMP  1572864
#define OFF_USPEC 2097152
#define OFF_ESPEC 2098176
#define OFF_ERR   2099200
#define OFF_CAL   2623488

// ---- scratch -------------------------------------------------------------
__device__ float g_T[(size_t)NIMG * HH * 64];   // [img][x][0:32]=Tr, [32:64]=Ti
__device__ float g_mre[(size_t)NIMG * MODES];
__device__ float g_mim[(size_t)NIMG * MODES];
__device__ float g_total[BC];

// ===========================================================================
// Stage 1: T[x][k] = sum_y P[x][y] * exp(-2*pi*i*k*y/256), k = 0..31.
// Folded over y with a uniform 129-entry table (endpoints 0.5-scaled):
//   e[y] = P[y]+P[(256-y)&255], o[y] = P[(256-y)&255]-P[y], y = 0..128
//   Tr[k] = sum_y e[y]*c(y,k) ;  Ti[k] = sum_y o[y]*s(y,k)
//
// CTA = 128 threads, 1 image, 64-row tiles. Thread: kg=tid&3 -> k = kg*8..+7,
// rg=tid>>2 -> rows rg and rg+32.  32 scalar FMAs per y per thread.
// Dynamic smem: cosT[129*32] + sinT[129*32] (33,024 B) + Pt 64x260 (66,560 B).
// ===========================================================================
#define S1_COS_OFF  0
#define S1_SIN_OFF  (129 * 32)
#define S1_PT_OFF   (2 * 129 * 32)
#define S1_PTSTRIDE 260
#define S1_SMEM     ((2 * 129 * 32 + 64 * S1_PTSTRIDE) * 4)   // 99,584 B

__global__ __launch_bounds__(128) void k_stage1(const float* __restrict__ pred,
                                                const float* __restrict__ gt)
{
    extern __shared__ float smem[];
    float* cosT = smem + S1_COS_OFF;     // [129][32]
    float* sinT = smem + S1_SIN_OFF;     // [129][32]
    float* Pt   = smem + S1_PT_OFF;      // [64][260]

    const int img = blockIdx.x;
    const float* src = (img < BC) ? (pred + (size_t)img * IMG_ELEMS)
                                  : (gt   + (size_t)(img - BC) * IMG_ELEMS);
    const int tid = threadIdx.x;

    // twiddle tables; endpoint rows (y=0, y=128) scaled by 0.5
    for (int i = tid; i < 129 * 32; i += 128) {
        int y = i >> 5;
        int k = i & 31;
        float a  = (float)((y * k) & 255) * (1.0f / 128.0f);
        float sc = (y == 0 || y == 128) ? 0.5f : 1.0f;
        cosT[i] = sc * cospif(a);
        sinT[i] = sc * sinpif(a);
    }

    const int kg = tid & 3;          // k base = kg*8
    const int rg = tid >> 2;         // rows rg and rg+32 within tile
    float* Trow = g_T + (size_t)img * HH * 64;

    for (int tile = 0; tile < 4; ++tile) {
        const int x0 = tile * 64;
        __syncthreads();             // tables ready (tile 0) / Pt readers done
        {
            const float4* g4 = (const float4*)(src + (size_t)x0 * HH);
            for (int i = tid; i < 64 * 64; i += 128) {
                int row = i >> 6;
                int col = (i & 63) * 4;
                *(float4*)&Pt[row * S1_PTSTRIDE + col] = g4[i];
            }
        }
        __syncthreads();

        // accumulators: 2 rows x 8 k x (tr, ti)
        float4 trA0, trA1, tiA0, tiA1, trB0, trB1, tiB0, tiB1;
        trA0 = trA1 = tiA0 = tiA1 = make_float4(0.f, 0.f, 0.f, 0.f);
        trB0 = trB1 = tiB0 = tiB1 = make_float4(0.f, 0.f, 0.f, 0.f);

        const float* rowA = &Pt[rg * S1_PTSTRIDE];
        const float* rowB = &Pt[(rg + 32) * S1_PTSTRIDE];

        #pragma unroll 2
        for (int y = 0; y <= 128; ++y) {
            const int by = (256 - y) & 255;
            float a0 = rowA[y], b0 = rowA[by];
            float a1 = rowB[y], b1 = rowB[by];
            float e0 = a0 + b0, o0 = b0 - a0;
            float e1 = a1 + b1, o1 = b1 - a1;

            const float* cp = &cosT[y * 32 + kg * 8];
            const float* sp = &sinT[y * 32 + kg * 8];
            float4 c0 = *(const float4*)cp;
            float4 c1 = *(const float4*)(cp + 4);
            float4 s0 = *(const float4*)sp;
            float4 s1 = *(const float4*)(sp + 4);

            trA0.x = fmaf(e0, c0.x, trA0.x); trA0.y = fmaf(e0, c0.y, trA0.y);
            trA0.z = fmaf(e0, c0.z, trA0.z); trA0.w = fmaf(e0, c0.w, trA0.w);
            trA1.x = fmaf(e0, c1.x, trA1.x); trA1.y = fmaf(e0, c1.y, trA1.y);
            trA1.z = fmaf(e0, c1.z, trA1.z); trA1.w = fmaf(e0, c1.w, trA1.w);
            tiA0.x = fmaf(o0, s0.x, tiA0.x); tiA0.y = fmaf(o0, s0.y, tiA0.y);
            tiA0.z = fmaf(o0, s0.z, tiA0.z); tiA0.w = fmaf(o0, s0.w, tiA0.w);
            tiA1.x = fmaf(o0, s1.x, tiA1.x); tiA1.y = fmaf(o0, s1.y, tiA1.y);
            tiA1.z = fmaf(o0, s1.z, tiA1.z); tiA1.w = fmaf(o0, s1.w, tiA1.w);

            trB0.x = fmaf(e1, c0.x, trB0.x); trB0.y = fmaf(e1, c0.y, trB0.y);
            trB0.z = fmaf(e1, c0.z, trB0.z); trB0.w = fmaf(e1, c0.w, trB0.w);
            trB1.x = fmaf(e1, c1.x, trB1.x); trB1.y = fmaf(e1, c1.y, trB1.y);
            trB1.z = fmaf(e1, c1.z, trB1.z); trB1.w = fmaf(e1, c1.w, trB1.w);
            tiB0.x = fmaf(o1, s0.x, tiB0.x); tiB0.y = fmaf(o1, s0.y, tiB0.y);
            tiB0.z = fmaf(o1, s0.z, tiB0.z); tiB0.w = fmaf(o1, s0.w, tiB0.w);
            tiB1.x = fmaf(o1, s1.x, tiB1.x); tiB1.y = fmaf(o1, s1.y, tiB1.y);
            tiB1.z = fmaf(o1, s1.z, tiB1.z); tiB1.w = fmaf(o1, s1.w, tiB1.w);
        }

        // store: Tr at cols [kg*8 .. +7], Ti at +32
        {
            float* dA = Trow + (size_t)(x0 + rg) * 64 + kg * 8;
            float* dB = Trow + (size_t)(x0 + rg + 32) * 64 + kg * 8;
            ((float4*)dA)[0] = trA0;  ((float4*)(dA + 4))[0]  = trA1;
            ((float4*)(dA + 32))[0] = tiA0; ((float4*)(dA + 36))[0] = tiA1;
            ((float4*)dB)[0] = trB0;  ((float4*)(dB + 4))[0]  = trB1;
            ((float4*)(dB + 32))[0] = tiB0; ((float4*)(dB + 36))[0] = tiB1;
        }
    }
}

// ===========================================================================
// Stage 2: modes[k1][k2] = sum_x exp(-2*pi*i*k1*x/256) * T[x][k2], folded in x.
//   re = sum_{x=1..127} c*Etr + s*Oti  (+ endpoints)
//   im = sum_{x=1..127} c*Eti - s*Otr  (+ endpoints)
// One CTA per image; 4 warps = k1 groups of 8, lane = k2.   [validated @515us]
// ===========================================================================
__global__ __launch_bounds__(128) void k_stage2(float* __restrict__ out)
{
    __shared__ float costab[256];
    __shared__ float red[128];

    const int img = blockIdx.x;
    const int tid = threadIdx.x;

    for (int i = tid; i < 256; i += 128)
        costab[i] = cospif((float)i * (1.0f / 128.0f));
    __syncthreads();

    const int lane = tid & 31;           // k2
    const int k1b  = (tid >> 5) * 8;     // k1 base for this warp
    const float* T = g_T + (size_t)img * HH * 64;

    float re[8], im[8];
    #pragma unroll
    for (int i = 0; i < 8; ++i) { re[i] = 0.f; im[i] = 0.f; }

    for (int x = 1; x <= 127; ++x) {
        float tra = T[x * 64 + lane];
        float tia = T[x * 64 + 32 + lane];
        float trb = T[(256 - x) * 64 + lane];
        float tib = T[(256 - x) * 64 + 32 + lane];
        float Etr = tra + trb, Otr = tra - trb;
        float Eti = tia + tib, Oti = tia - tib;
        int m = (x * k1b) & 255;
        #pragma unroll
        for (int i = 0; i < 8; ++i) {
            float c = costab[m];
            float s = costab[(m + 192) & 255];     // sin(t) = cos(t - pi/2)
            re[i] += c * Etr + s * Oti;
            im[i] += c * Eti - s * Otr;
            m = (m + x) & 255;
        }
    }
    // endpoints x=0 and x=128
    {
        float tr0   = T[lane],             ti0   = T[32 + lane];
        float tr128 = T[128 * 64 + lane],  ti128 = T[128 * 64 + 32 + lane];
        #pragma unroll
        for (int i = 0; i < 8; ++i) {
            float sgn = ((k1b + i) & 1) ? -1.0f : 1.0f;
            re[i] += tr0 + sgn * tr128;
            im[i] += ti0 + sgn * ti128;
        }
    }

    const size_t mbase = (size_t)img * MODES;
    float esum = 0.f;
    #pragma unroll
    for (int i = 0; i < 8; ++i) {
        int idx = (k1b + i) * 32 + lane;
        g_mre[mbase + idx] = re[i];
        g_mim[mbase + idx] = im[i];
        if (img < BC) {
            float en = re[i] * re[i] + im[i] * im[i];
            out[OFF_EN + (size_t)img * MODES + idx] = en;
            esum += en;
        }
    }

    if (img < BC) {
        red[tid] = esum;
        __syncthreads();
        for (int s = 64; s > 0; s >>= 1) {
            if (tid < s) red[tid] += red[tid + s];
            __syncthreads();
        }
        if (tid == 0) g_total[img] = red[0];
    }
}

// ===========================================================================
// MLP per mode (2->64->32->1, softplus) + element-wise outputs. [validated]
// ===========================================================================
__global__ __launch_bounds__(256) void k_mlp(
    const float* __restrict__ W1, const float* __restrict__ b1,
    const float* __restrict__ W2, const float* __restrict__ b2,
    const float* __restrict__ W3, const float* __restrict__ b3,
    float* __restrict__ out)
{
    __shared__ float sW1[128];
    __shared__ float sb1[64];
    __shared__ float sW2[2048];   // [64][32]
    __shared__ float sb2[32];
    __shared__ float sW3[32];
    __shared__ float sb3;

    const int tid = threadIdx.x;
    for (int i = tid; i < 128;  i += 256) sW1[i] = W1[i];
    for (int i = tid; i < 2048; i += 256) sW2[i] = W2[i];
    if (tid < 64) sb1[tid] = b1[tid];
    if (tid < 32) { sb2[tid] = b2[tid]; sW3[tid] = W3[tid]; }
    if (tid == 0) sb3 = b3[0];
    __syncthreads();

    const size_t g = (size_t)blockIdx.x * 256 + tid;
    const int bc = (int)(g >> 10);

    float xr = g_mre[g];
    float xv = g_mim[g];
    float gr = g_mre[(size_t)BC * MODES + g];
    float gi = g_mim[(size_t)BC * MODES + g];

    float acc[32];
    #pragma unroll
    for (int j = 0; j < 32; ++j) acc[j] = sb2[j];

    #pragma unroll 4
    for (int i = 0; i < 64; ++i) {
        float h = fmaf(xr, sW1[i], fmaf(xv, sW1[64 + i], sb1[i]));
        h = fmaxf(h, 0.f);
        const float* w2 = &sW2[i * 32];
        #pragma unroll
        for (int j = 0; j < 32; ++j) acc[j] = fmaf(h, w2[j], acc[j]);
    }

    float z = sb3;
    #pragma unroll
    for (int j = 0; j < 32; ++j) z = fmaf(fmaxf(acc[j], 0.f), sW3[j], z);

    float u = fmaxf(z, 0.f) + log1pf(expf(-fabsf(z)));   // softplus

    float en   = xr * xr + xv * xv;
    float frac = en / (g_total[bc] + FEPS);
    float dr = xr - gr, di = xv - gi;
    float err = dr * dr + di * di;

    out[OFF_UNC  + g] = u;
    out[OFF_FRAC + g] = frac;
    out[OFF_WIMP + g] = frac * u;
    out[OFF_ERR  + g] = err;
}

// ===========================================================================
// Per-mode reductions: spectra means + Pearson(u, err) over 512 (b,c).
// ===========================================================================
__global__ __launch_bounds__(128) void k_pearson(float* __restrict__ out)
{
    __shared__ float su[512], se[512];
    __shared__ float r1[128], r2[128], r3[128];

    const int mode = blockIdx.x;
    const int tid  = threadIdx.x;

    const float* unc = out + OFF_UNC;
    const float* err = out + OFF_ERR;
    const float* eng = out + OFF_EN;

    float lu = 0.f, le = 0.f, len = 0.f;
    #pragma unroll
    for (int r = 0; r < 4; ++r) {
        int bc = tid + r * 128;
        float u = unc[(size_t)bc * MODES + mode];
        float e = err[(size_t)bc * MODES + mode];
        float n = eng[(size_t)bc * MODES + mode];
        su[bc] = u; se[bc] = e;
        lu += u; le += e; len += n;
    }
    r1[tid] = lu; r2[tid] = le; r3[tid] = len;
    __syncthreads();
    for (int s = 64; s > 0; s >>= 1) {
        if (tid < s) { r1[tid] += r1[tid + s]; r2[tid] += r2[tid + s]; r3[tid] += r3[tid + s]; }
        __syncthreads();
    }
    const float SU = r1[0], SE = r2[0], SEN = r3[0];
    const float mu = SU * (1.0f / 512.0f);
    const float me = SE * (1.0f / 512.0f);
    __syncthreads();

    float s1 = 0.f, s2 = 0.f, s3 = 0.f;
    #pragma unroll
    for (int r = 0; r < 4; ++r) {
        int bc = tid + r * 128;
        float uc = su[bc] - mu;
        float ec = se[bc] - me;
        s1 += uc * ec; s2 += uc * uc; s3 += ec * ec;
    }
    r1[tid] = s1; r2[tid] = s2; r3[tid] = s3;
    __syncthreads();
    for (int s = 64; s > 0; s >>= 1) {
        if (tid < s) { r1[tid] += r1[tid + s]; r2[tid] += r2[tid + s]; r3[tid] += r3[tid + s]; }
        __syncthreads();
    }

    if (tid == 0) {
        out[OFF_USPEC + mode] = SU  * (1.0f / 512.0f);
        out[OFF_ESPEC + mode] = SEN * (1.0f / 512.0f);
        float den = sqrtf(r2[0] * r3[0]);
        out[OFF_CAL + mode] = r1[0] / (den + FEPS);
    }
}

// ===========================================================================
extern "C" void kernel_launch(void* const* d_in, const int* in_sizes, int n_in,
                              void* d_out, int out_size)
{
    (void)in_sizes; (void)n_in; (void)out_size;
    const float* pred = (const float*)d_in[0];
    // d_in[1] ('uncertainty') is unused by the reference computation.
    const float* gt   = (const float*)d_in[2];
    const float* W1   = (const float*)d_in[3];
    const float* b1   = (const float*)d_in[4];
    const float* W2   = (const float*)d_in[5];
    const float* b2   = (const float*)d_in[6];
    const float* W3   = (const float*)d_in[7];
    const float* b3   = (const float*)d_in[8];
    float* out = (float*)d_out;

    cudaFuncSetAttribute(k_stage1, cudaFuncAttributeMaxDynamicSharedMemorySize,
                         S1_SMEM);

    k_stage1 <<<NIMG, 128, S1_SMEM>>>(pred, gt);
    k_stage2 <<<NIMG, 128>>>(out);
    k_mlp    <<<2048, 256>>>(W1, b1, W2, b2, W3, b3, out);
    k_pearson<<<MODES, 128>>>(out);
}